// round 4
// baseline (speedup 1.0000x reference)
#include <cuda_runtime.h>
#include <math.h>
#include <stdint.h>

#define BB 8
#define NN 2500
#define EE 100
#define FF 50
#define YY 8922
#define KK 9
#define BY (BB*YY)

// attention tiling
#define TY   16
#define CN   128
#define NCH  20        // ceil(2500/128)
#define HP   52        // h row pad: LDS.128 conflict-free (stride 52)
#define NPAD 2501

typedef unsigned long long ull;

__device__ float g_h[BB*NN*FF];     // conv output h[b][n][f]
__device__ float g_loss[BY];        // per-(b,y) BCE terms

__device__ __forceinline__ void ffma2(ull &d, ull a, ull b) {
    asm("fma.rn.f32x2 %0, %1, %2, %0;" : "+l"(d) : "l"(a), "l"(b));
}
__device__ __forceinline__ ull pk2(float v) {
    ull r; unsigned u = __float_as_uint(v);
    asm("mov.b64 %0, {%1, %2};" : "=l"(r) : "r"(u), "r"(u));
    return r;
}
__device__ __forceinline__ float lo32(ull v){ return __uint_as_float((unsigned)v); }
__device__ __forceinline__ float hi32(ull v){ return __uint_as_float((unsigned)(v>>32)); }
__device__ __forceinline__ float sum2(ull v){ return lo32(v) + hi32(v); }

__device__ __forceinline__ void cp_commit(){ asm volatile("cp.async.commit_group;"); }
template<int W> __device__ __forceinline__ void cp_wait(){ asm volatile("cp.async.wait_group %0;" :: "n"(W)); }

// ======================= Kernel 1: embed + conv1d(K=9,SAME) + tanh =======================
// grid (27, 8), 384 threads. thread = (tn in 0..95, eq in 0..3). 96-n tile.
#define CVN 96
__global__ __launch_bounds__(384, 1)
void conv_kernel(const int* __restrict__ x, const float* __restrict__ embW,
                 const float* __restrict__ convW, const float* __restrict__ convB) {
    extern __shared__ float sm[];
    float* emb = sm;                    // 104*101 = 10504
    float* wsm = emb + 104*101;         // 900*50 = 45000, wsm[(e*9+k)*50+f]
    int*  toks = (int*)(wsm + 45000);   // 104

    int b = blockIdx.y, base = blockIdx.x * CVN, tid = threadIdx.x;

    if (tid < CVN + 8) {
        int n = base - 4 + tid;
        toks[tid] = (n >= 0 && n < NN) ? x[b*NN + n] : -1;
    }
    __syncthreads();
    // W transposed: wsm[(e*9+k)*50 + f] = convW[f*900 + e*9 + k]
    for (int j = tid; j < FF*EE*KK; j += 384) {
        int f = j / 900, r = j - f*900;
        wsm[r*FF + f] = convW[j];
    }
    // embedding gather (pad 101 -> conflict-free scalar reads)
    for (int j = tid; j < (CVN+8)*EE; j += 384) {
        int row = j / EE, c = j - row*EE;
        int tk = toks[row];
        emb[row*101 + c] = (tk >= 0) ? embW[(size_t)tk*EE + c] : 0.f;
    }
    __syncthreads();

    int tn = tid % CVN;       // 96 = 3 warps per eq -> warp-uniform eq, conflict-free emb
    int eq = tid / CVN;       // e-quarter

    ull acc[25];
    #pragma unroll
    for (int q = 0; q < 25; q++) acc[q] = 0ull;

    for (int ee = 0; ee < 25; ee++) {
        int e = eq*25 + ee;
        #pragma unroll
        for (int k = 0; k < KK; k++) {
            ull v = pk2(emb[(tn + k)*101 + e]);
            const ull* wr = (const ull*)&wsm[(e*KK + k)*FF];
            #pragma unroll
            for (int q = 0; q < 25; q++) ffma2(acc[q], wr[q], v);
        }
    }
    __syncthreads();
    // partial reduction over e-quarters: alias scratch onto emb/wsm region
    float* part = sm;  // 3*96*50 = 14400 floats
    if (eq > 0) {
        float* p = part + (eq-1)*CVN*FF + tn*FF;
        #pragma unroll
        for (int q = 0; q < 25; q++) {
            p[2*q]   = lo32(acc[q]);
            p[2*q+1] = hi32(acc[q]);
        }
    }
    __syncthreads();
    if (eq == 0) {
        int n = base + tn;
        if (n < NN) {
            float* dst = &g_h[((size_t)b*NN + n)*FF];
            const float* p0 = part + tn*FF;
            const float* p1 = part + CVN*FF + tn*FF;
            const float* p2 = part + 2*CVN*FF + tn*FF;
            #pragma unroll
            for (int q = 0; q < 25; q++) {
                float a0 = lo32(acc[q]) + p0[2*q]   + p1[2*q]   + p2[2*q]   + convB[2*q];
                float a1 = hi32(acc[q]) + p0[2*q+1] + p1[2*q+1] + p2[2*q+1] + convB[2*q+1];
                dst[2*q]   = tanhf(a0);
                dst[2*q+1] = tanhf(a1);
            }
        }
    }
}

// ======================= Kernel 2: fused scores -> softmax -> alpha -> logits =======================
__device__ __forceinline__ void load_chunk(float* hs_buf, const float* hb, int c, int tid) {
    int n0 = c * CN;
    for (int idx = tid; idx < CN*25; idx += 512) {
        int n = idx / 25, f2 = idx - n*25;
        int gn = n0 + n;
        int ok = (gn < NN) ? 8 : 0;
        const float* src = hb + (size_t)(gn < NN ? gn : 0)*FF + 2*f2;
        uint32_t dst = (uint32_t)__cvta_generic_to_shared(&hs_buf[n*HP + 2*f2]);
        asm volatile("cp.async.ca.shared.global [%0], [%1], 8, %2;" :: "r"(dst), "l"(src), "r"(ok));
    }
}

__global__ __launch_bounds__(512, 1)
void attn_kernel(const float* __restrict__ Uw, const float* __restrict__ finW,
                 const float* __restrict__ finB, const float* __restrict__ tgt,
                 float* __restrict__ yhat_out, float* __restrict__ alpha_out) {
    extern __shared__ float sm[];
    float* s   = sm;                     // TY*NPAD = 40016
    float* hs  = s + TY*NPAD;            // 2*CN*HP = 13312
    float* Us  = hs + 2*CN*HP;           // TY*52 = 832
    float* Fs  = Us + TY*52;             // 832
    float* red = Fs + TY*52;             // 64

    int b = blockIdx.y;
    int y0 = blockIdx.x * TY;
    int tid = threadIdx.x;
    const float* hb = g_h + (size_t)b*NN*FF;

    // stage U/final rows (stride 52, zero-pad invalid y and tail)
    for (int j = tid; j < TY*52; j += 512) {
        int t = j / 52, f = j - t*52;
        int y = y0 + t;
        float u = 0.f, fv = 0.f;
        if (y < YY && f < FF) {
            u  = Uw[(size_t)y*FF + f];
            fv = finW[(size_t)y*FF + f];
        }
        Us[j] = u; Fs[j] = fv;
    }

    int tn = tid & 127, tt = tid >> 7;   // thread: n = tn (1 per chunk), ty rows tt*4..tt*4+3
    const float* u0 = Us + (tt*4+0)*52;
    const float* u1 = Us + (tt*4+1)*52;
    const float* u2 = Us + (tt*4+2)*52;
    const float* u3 = Us + (tt*4+3)*52;

    // ---------------- Phase A: scores ----------------
    load_chunk(hs, hb, 0, tid); cp_commit();
    for (int c = 0; c < NCH; c++) {
        if (c + 1 < NCH) { load_chunk(hs + ((c+1)&1)*CN*HP, hb, c+1, tid); cp_commit(); cp_wait<1>(); }
        else cp_wait<0>();
        __syncthreads();
        const float* hrow = hs + (c&1)*CN*HP + tn*HP;
        ull a0=0, a1=0, a2=0, a3=0;
        #pragma unroll
        for (int q = 0; q < 12; q++) {
            ulonglong2 hv = *(const ulonglong2*)(hrow + 4*q);
            ulonglong2 v0 = *(const ulonglong2*)(u0 + 4*q);
            ffma2(a0, v0.x, hv.x); ffma2(a0, v0.y, hv.y);
            ulonglong2 v1 = *(const ulonglong2*)(u1 + 4*q);
            ffma2(a1, v1.x, hv.x); ffma2(a1, v1.y, hv.y);
            ulonglong2 v2 = *(const ulonglong2*)(u2 + 4*q);
            ffma2(a2, v2.x, hv.x); ffma2(a2, v2.y, hv.y);
            ulonglong2 v3 = *(const ulonglong2*)(u3 + 4*q);
            ffma2(a3, v3.x, hv.x); ffma2(a3, v3.y, hv.y);
        }
        {   // remainder f = 48,49
            ull hv = *(const ull*)(hrow + 48);
            ffma2(a0, *(const ull*)(u0 + 48), hv);
            ffma2(a1, *(const ull*)(u1 + 48), hv);
            ffma2(a2, *(const ull*)(u2 + 48), hv);
            ffma2(a3, *(const ull*)(u3 + 48), hv);
        }
        int gn = c*CN + tn;
        if (gn < NN) {
            s[(tt*4+0)*NPAD + gn] = sum2(a0);
            s[(tt*4+1)*NPAD + gn] = sum2(a1);
            s[(tt*4+2)*NPAD + gn] = sum2(a2);
            s[(tt*4+3)*NPAD + gn] = sum2(a3);
        }
        __syncthreads();
    }

    // prefetch chunk 0 for phase C while softmax runs
    load_chunk(hs, hb, 0, tid); cp_commit();

    // ---------------- Phase B: softmax + alpha write (one warp per row) ----------------
    {
        int w = tid >> 5, lane = tid & 31;   // 16 warps == TY rows
        float* sr = s + w*NPAD;
        float m = -1e30f;
        for (int i = lane; i < NN; i += 32) m = fmaxf(m, sr[i]);
        #pragma unroll
        for (int o = 16; o; o >>= 1) m = fmaxf(m, __shfl_xor_sync(~0u, m, o));
        float d = 0.f;
        for (int i = lane; i < NN; i += 32) { float e = __expf(sr[i] - m); sr[i] = e; d += e; }
        #pragma unroll
        for (int o = 16; o; o >>= 1) d += __shfl_xor_sync(~0u, d, o);
        float inv = 1.f / d;
        int y = y0 + w;
        bool valid = (y < YY);
        float* ao = alpha_out + ((size_t)b*YY + (valid ? y : 0))*NN;
        for (int i = lane; i < NN; i += 32) {
            float al = sr[i] * inv;
            sr[i] = al;
            if (valid) ao[i] = al;
        }
    }
    __syncthreads();

    // ---------------- Phase C: logits = sum_n alpha * (h . final) ----------------
    const float* f0 = Fs + (tt*4+0)*52;
    const float* f1 = Fs + (tt*4+1)*52;
    const float* f2 = Fs + (tt*4+2)*52;
    const float* f3 = Fs + (tt*4+3)*52;
    float lg0=0.f, lg1=0.f, lg2=0.f, lg3=0.f;
    for (int c = 0; c < NCH; c++) {
        if (c + 1 < NCH) { load_chunk(hs + ((c+1)&1)*CN*HP, hb, c+1, tid); cp_commit(); cp_wait<1>(); }
        else cp_wait<0>();
        __syncthreads();
        const float* hrow = hs + (c&1)*CN*HP + tn*HP;
        ull a0=0, a1=0, a2=0, a3=0;
        #pragma unroll
        for (int q = 0; q < 12; q++) {
            ulonglong2 hv = *(const ulonglong2*)(hrow + 4*q);
            ulonglong2 v0 = *(const ulonglong2*)(f0 + 4*q);
            ffma2(a0, v0.x, hv.x); ffma2(a0, v0.y, hv.y);
            ulonglong2 v1 = *(const ulonglong2*)(f1 + 4*q);
            ffma2(a1, v1.x, hv.x); ffma2(a1, v1.y, hv.y);
            ulonglong2 v2 = *(const ulonglong2*)(f2 + 4*q);
            ffma2(a2, v2.x, hv.x); ffma2(a2, v2.y, hv.y);
            ulonglong2 v3 = *(const ulonglong2*)(f3 + 4*q);
            ffma2(a3, v3.x, hv.x); ffma2(a3, v3.y, hv.y);
        }
        {
            ull hv = *(const ull*)(hrow + 48);
            ffma2(a0, *(const ull*)(f0 + 48), hv);
            ffma2(a1, *(const ull*)(f1 + 48), hv);
            ffma2(a2, *(const ull*)(f2 + 48), hv);
            ffma2(a3, *(const ull*)(f3 + 48), hv);
        }
        int gn = c*CN + tn;
        if (gn < NN) {
            lg0 += s[(tt*4+0)*NPAD + gn] * sum2(a0);
            lg1 += s[(tt*4+1)*NPAD + gn] * sum2(a1);
            lg2 += s[(tt*4+2)*NPAD + gn] * sum2(a2);
            lg3 += s[(tt*4+3)*NPAD + gn] * sum2(a3);
        }
        __syncthreads();
    }

    // reduce lg over the 128 tn-threads (4 warps per tt)
    {
        int w = tid >> 5, lane = tid & 31;
        float v[4] = {lg0, lg1, lg2, lg3};
        #pragma unroll
        for (int r = 0; r < 4; r++) {
            float t = v[r];
            #pragma unroll
            for (int o = 16; o; o >>= 1) t += __shfl_xor_sync(~0u, t, o);
            if (lane == 0) red[w*4 + r] = t;
        }
    }
    __syncthreads();

    if (tid < TY) {
        int tq = tid >> 2, r = tid & 3;      // ty row = tq*4 + r == tid
        float v = red[(tq*4+0)*4 + r] + red[(tq*4+1)*4 + r]
                + red[(tq*4+2)*4 + r] + red[(tq*4+3)*4 + r];
        int y = y0 + tid;
        if (y < YY) {
            float logit = v + finB[y];
            float p = 1.f / (1.f + __expf(-logit));
            yhat_out[(size_t)b*YY + y] = p;
            float pc = fminf(fmaxf(p, 1e-7f), 1.f - 1e-7f);
            float t = tgt[(size_t)b*YY + y];
            g_loss[(size_t)b*YY + y] = -(t*logf(pc) + (1.f - t)*log1pf(-pc));
        }
    }
}

// ======================= Kernel 3: deterministic loss reduction =======================
__global__ void loss_kernel(float* __restrict__ out) {
    __shared__ float r[256];
    int tid = threadIdx.x;
    float a = 0.f;
    for (int i = tid; i < BY; i += 256) a += g_loss[i];
    r[tid] = a;
    __syncthreads();
    for (int st = 128; st > 0; st >>= 1) {
        if (tid < st) r[tid] += r[tid + st];
        __syncthreads();
    }
    if (tid == 0) out[BY] = r[0] / (float)BY;
}

// ======================= Launch =======================
extern "C" void kernel_launch(void* const* d_in, const int* in_sizes, int n_in,
                              void* d_out, int out_size) {
    const int*   x      = (const int*)d_in[0];
    const float* target = (const float*)d_in[1];
    const float* embW   = (const float*)d_in[2];
    const float* convW  = (const float*)d_in[3];
    const float* convB  = (const float*)d_in[4];
    const float* Uw     = (const float*)d_in[5];
    const float* finW   = (const float*)d_in[6];
    const float* finB   = (const float*)d_in[7];
    float* out = (float*)d_out;
    float* yhat  = out;            // [B,Y]
    float* alpha = out + BY + 1;   // [B,Y,N]; out[BY] = loss

    const int conv_smem = (104*101 + 45000)*4 + 104*4;                   // 222432
    const int attn_smem = (TY*NPAD + 2*CN*HP + 2*TY*52 + 64)*4;          // 220224

    cudaFuncSetAttribute(conv_kernel, cudaFuncAttributeMaxDynamicSharedMemorySize, conv_smem);
    cudaFuncSetAttribute(attn_kernel, cudaFuncAttributeMaxDynamicSharedMemorySize, attn_smem);

    conv_kernel<<<dim3((NN + CVN - 1)/CVN, BB), 384, conv_smem>>>(x, embW, convW, convB);
    attn_kernel<<<dim3((YY + TY - 1)/TY, BB), 512, attn_smem>>>(Uw, finW, finB, target, yhat, alpha);
    loss_kernel<<<1, 256>>>(out);
}